// round 1
// baseline (speedup 1.0000x reference)
#include <cuda_runtime.h>
#include <cuda_bf16.h>
#include <math.h>

// Problem constants
#define BATCH 4096
#define D_IN  1024
#define DF    256
#define NM    10
#define NK    8
#define NMK   80
#define LOG2PI_F 1.8378770664093453f

// Scratch (no cudaMalloc allowed)
__device__ float g_featsT[DF * BATCH];          // [256][4096] feats transposed
__device__ float g_Ainv[NMK * DF * DF];         // 80 x 256 x 256 triangular inverses
__device__ float g_quad[NMK * BATCH];           // [80][4096] Mahalanobis terms
__device__ float g_c1[NMK];                     // -0.5 * w
__device__ float g_c2[NMK];                     // w * (-0.5*DF*log2pi - logdet)

// ---------------------------------------------------------------------------
// Kernel 1: feats^T = relu(x @ W + b)^T   (stored transposed for kernel 3)
// Tile: 128 (b) x 64 (n), K-tile 16, 256 threads, micro 8x4
// ---------------------------------------------------------------------------
__global__ __launch_bounds__(256) void k_feats(const float* __restrict__ x,
                                               const float* __restrict__ W,
                                               const float* __restrict__ bias)
{
    const int b0 = blockIdx.x * 128;
    const int n0 = blockIdx.y * 64;
    const int tid = threadIdx.x;
    const int tx = tid & 15;   // n direction (x4)
    const int ty = tid >> 4;   // b direction (x8)

    __shared__ float Xs[16][128];  // k-major (transposed)
    __shared__ float Ws[16][64];

    float acc[8][4];
#pragma unroll
    for (int i = 0; i < 8; i++)
#pragma unroll
        for (int j = 0; j < 4; j++) acc[i][j] = 0.0f;

    for (int kt = 0; kt < D_IN; kt += 16) {
        __syncthreads();
        // load X tile [128 b][16 k] -> Xs[k][b]
#pragma unroll
        for (int it = 0; it < 2; it++) {
            int v = tid + it * 256;          // 0..511 float4 slots
            int row = v >> 2;                // 0..127
            int c4  = (v & 3) * 4;           // 0,4,8,12
            float4 xv = *(const float4*)&x[(size_t)(b0 + row) * D_IN + kt + c4];
            Xs[c4 + 0][row] = xv.x;
            Xs[c4 + 1][row] = xv.y;
            Xs[c4 + 2][row] = xv.z;
            Xs[c4 + 3][row] = xv.w;
        }
        // load W tile [16 k][64 n]
        {
            int row = tid >> 4;              // 0..15
            int c4  = (tid & 15) * 4;        // 0..60
            *(float4*)&Ws[row][c4] = *(const float4*)&W[(size_t)(kt + row) * DF + n0 + c4];
        }
        __syncthreads();
#pragma unroll
        for (int k = 0; k < 16; k++) {
            float av[8], wv[4];
            float4 a0 = *(float4*)&Xs[k][ty * 8];
            float4 a1 = *(float4*)&Xs[k][ty * 8 + 4];
            av[0] = a0.x; av[1] = a0.y; av[2] = a0.z; av[3] = a0.w;
            av[4] = a1.x; av[5] = a1.y; av[6] = a1.z; av[7] = a1.w;
            float4 w4 = *(float4*)&Ws[k][tx * 4];
            wv[0] = w4.x; wv[1] = w4.y; wv[2] = w4.z; wv[3] = w4.w;
#pragma unroll
            for (int i = 0; i < 8; i++)
#pragma unroll
                for (int j = 0; j < 4; j++)
                    acc[i][j] = fmaf(av[i], wv[j], acc[i][j]);
        }
    }
    // epilogue: bias + relu, store transposed
#pragma unroll
    for (int j = 0; j < 4; j++) {
        int n = n0 + tx * 4 + j;
        float bb = bias[n];
#pragma unroll
        for (int i = 0; i < 8; i++) {
            float v = acc[i][j] + bb;
            v = v > 0.0f ? v : 0.0f;
            g_featsT[(size_t)n * BATCH + b0 + ty * 8 + i] = v;
        }
    }
}

// ---------------------------------------------------------------------------
// Kernel 2: triangular inverse of L = tril(covs[mk]) per component.
// Grid (80, 8), 256 threads (8 warps). Each warp computes 4 adjacent columns
// of L^{-1} by forward substitution (coalesced row loads, 4-wide butterfly
// reduction). Upper triangle of g_Ainv is explicitly zeroed.
// ---------------------------------------------------------------------------
__global__ __launch_bounds__(256) void k_trinv(const float* __restrict__ covs)
{
    const int mk = blockIdx.x;
    const int cg = blockIdx.y;                 // 0..7
    const int w = threadIdx.x >> 5;
    const int lane = threadIdx.x & 31;
    const int g = w * 8 + cg;                  // column group 0..63
    const int j0 = g * 4;

    const float* L = covs + (size_t)mk * DF * DF;
    float* Ai = g_Ainv + (size_t)mk * DF * DF;

    __shared__ float4 xck[8][DF];              // per-warp x values for its 4 columns
    float4* xc = xck[w];

    // zero rows strictly above j0 (float4 covers the 4 columns)
    for (int i = lane; i < j0; i += 32)
        *(float4*)&Ai[i * DF + j0] = make_float4(0.f, 0.f, 0.f, 0.f);

    for (int i = j0; i < DF; i++) {
        float4 s = make_float4(0.f, 0.f, 0.f, 0.f);
        for (int k = j0 + lane; k < i; k += 32) {
            float lik = L[i * DF + k];
            float4 xv = xc[k];
            s.x = fmaf(lik, xv.x, s.x);
            s.y = fmaf(lik, xv.y, s.y);
            s.z = fmaf(lik, xv.z, s.z);
            s.w = fmaf(lik, xv.w, s.w);
        }
#pragma unroll
        for (int off = 16; off > 0; off >>= 1) {
            s.x += __shfl_xor_sync(0xFFFFFFFFu, s.x, off);
            s.y += __shfl_xor_sync(0xFFFFFFFFu, s.y, off);
            s.z += __shfl_xor_sync(0xFFFFFFFFu, s.z, off);
            s.w += __shfl_xor_sync(0xFFFFFFFFu, s.w, off);
        }
        if (lane == 0) {
            float inv = 1.0f / L[i * DF + i];
            float4 xr;
            xr.x = ((i == j0 + 0 ? 1.0f : 0.0f) - s.x) * inv;
            xr.y = ((i == j0 + 1 ? 1.0f : 0.0f) - s.y) * inv;
            xr.z = ((i == j0 + 2 ? 1.0f : 0.0f) - s.z) * inv;
            xr.w = ((i == j0 + 3 ? 1.0f : 0.0f) - s.w) * inv;
            xc[i] = xr;
            *(float4*)&Ai[i * DF + j0] = xr;
        }
        __syncwarp();
    }
}

// ---------------------------------------------------------------------------
// Kernel 3 (hot): quad[mk][b] = sum_d ( sum_{d'} Ainv[d][d'] * diff[d'][b] )^2
// Grid (32 b-tiles, 80 mk). 256 threads. Z block 64(d) x 128(b), micro 4x8.
// Triangular skip: for d-block dblk, contraction runs only to 64*(dblk+1).
// ---------------------------------------------------------------------------
__global__ __launch_bounds__(256) void k_quad(const float* __restrict__ means)
{
    const int mk = blockIdx.y;
    const int b0 = blockIdx.x * 128;
    const int tid = threadIdx.x;
    const int tx = tid & 15;   // b direction (x8)
    const int ty = tid >> 4;   // d direction (x4)

    const float* Ai = g_Ainv + (size_t)mk * DF * DF;

    __shared__ float As[16][64];     // k-major A tile
    __shared__ float Ds[16][128];    // diff tile
    __shared__ float smean[DF];
    __shared__ float redq[16][128];

    smean[tid] = means[mk * DF + tid];

    float quadacc[8];
#pragma unroll
    for (int j = 0; j < 8; j++) quadacc[j] = 0.0f;

    for (int dblk = 0; dblk < 4; dblk++) {
        const int d0 = dblk * 64;
        const int kmax = d0 + 64;    // triangular limit (upper entries are 0)
        float acc[4][8];
#pragma unroll
        for (int r = 0; r < 4; r++)
#pragma unroll
            for (int j = 0; j < 8; j++) acc[r][j] = 0.0f;

        for (int kt = 0; kt < kmax; kt += 16) {
            __syncthreads();
            // A tile: rows d0..d0+63, cols kt..kt+15 -> As[k][d]
            {
                int row = tid >> 2;              // 0..63
                int c4  = (tid & 3) * 4;         // 0,4,8,12
                float4 av = *(const float4*)&Ai[(size_t)(d0 + row) * DF + kt + c4];
                As[c4 + 0][row] = av.x;
                As[c4 + 1][row] = av.y;
                As[c4 + 2][row] = av.z;
                As[c4 + 3][row] = av.w;
            }
            // D tile: Ds[k][b] = featsT[kt+k][b0+b] - mean[kt+k]
#pragma unroll
            for (int it = 0; it < 2; it++) {
                int v = tid + it * 256;          // 0..511 float4 slots
                int k  = v >> 5;                 // 0..15
                int b4 = (v & 31) * 4;           // 0..124
                float4 f = *(const float4*)&g_featsT[(size_t)(kt + k) * BATCH + b0 + b4];
                float m = smean[kt + k];
                f.x -= m; f.y -= m; f.z -= m; f.w -= m;
                *(float4*)&Ds[k][b4] = f;
            }
            __syncthreads();
#pragma unroll
            for (int k = 0; k < 16; k++) {
                float av[4], bv[8];
                float4 a4 = *(float4*)&As[k][ty * 4];
                av[0] = a4.x; av[1] = a4.y; av[2] = a4.z; av[3] = a4.w;
                float4 u0 = *(float4*)&Ds[k][tx * 8];
                float4 u1 = *(float4*)&Ds[k][tx * 8 + 4];
                bv[0] = u0.x; bv[1] = u0.y; bv[2] = u0.z; bv[3] = u0.w;
                bv[4] = u1.x; bv[5] = u1.y; bv[6] = u1.z; bv[7] = u1.w;
#pragma unroll
                for (int r = 0; r < 4; r++)
#pragma unroll
                    for (int j = 0; j < 8; j++)
                        acc[r][j] = fmaf(av[r], bv[j], acc[r][j]);
            }
        }
        // square-accumulate this d-block
#pragma unroll
        for (int r = 0; r < 4; r++)
#pragma unroll
            for (int j = 0; j < 8; j++)
                quadacc[j] = fmaf(acc[r][j], acc[r][j], quadacc[j]);
    }

    __syncthreads();
#pragma unroll
    for (int j = 0; j < 8; j++) redq[ty][tx * 8 + j] = quadacc[j];
    __syncthreads();
    if (tid < 128) {
        float s = 0.0f;
#pragma unroll
        for (int r = 0; r < 16; r++) s += redq[r][tid];
        g_quad[(size_t)mk * BATCH + b0 + tid] = s;
    }
}

// ---------------------------------------------------------------------------
// Kernel: per-component constants (logdet + softmax weights)
// ---------------------------------------------------------------------------
__global__ void k_prep(const float* __restrict__ covs,
                       const float* __restrict__ weights)
{
    const int mk = threadIdx.x;    // 0..127 launched, 0..79 valid
    float logdet = 0.0f;
    float wraw = 0.0f;
    if (mk < NMK) {
        const float* L = covs + (size_t)mk * DF * DF;
        for (int i = 0; i < DF; i++) logdet += logf(L[i * DF + i]);
        wraw = weights[mk];
    }
    // softmax over groups of 8 (K components) within each warp
    float mx = wraw;
#pragma unroll
    for (int off = 1; off < 8; off <<= 1)
        mx = fmaxf(mx, __shfl_xor_sync(0xFFFFFFFFu, mx, off));
    float e = (mk < NMK) ? expf(wraw - mx) : 0.0f;
    float sum = e;
#pragma unroll
    for (int off = 1; off < 8; off <<= 1)
        sum += __shfl_xor_sync(0xFFFFFFFFu, sum, off);
    if (mk < NMK) {
        float wsm = e / sum;
        g_c1[mk] = -0.5f * wsm;
        g_c2[mk] = wsm * (-0.5f * (float)DF * LOG2PI_F) - wsm * logdet;
    }
}

// ---------------------------------------------------------------------------
// Kernel: final output  out[b][m][k] = c1[mk]*quad[mk][b] + c2[mk]
// ---------------------------------------------------------------------------
__global__ __launch_bounds__(256) void k_out(float* __restrict__ out)
{
    int idx = blockIdx.x * 256 + threadIdx.x;
    if (idx >= BATCH * NMK) return;
    int b = idx / NMK;
    int r = idx - b * NMK;
    out[idx] = fmaf(g_c1[r], g_quad[(size_t)r * BATCH + b], g_c2[r]);
}

// ---------------------------------------------------------------------------
extern "C" void kernel_launch(void* const* d_in, const int* in_sizes, int n_in,
                              void* d_out, int out_size)
{
    const float* x       = (const float*)d_in[0];
    const float* W       = (const float*)d_in[1];
    const float* bias    = (const float*)d_in[2];
    const float* means   = (const float*)d_in[3];
    const float* covs    = (const float*)d_in[4];
    const float* weights = (const float*)d_in[5];
    float* out = (float*)d_out;

    k_feats<<<dim3(BATCH / 128, DF / 64), 256>>>(x, W, bias);
    k_trinv<<<dim3(NMK, 8), 256>>>(covs);
    k_prep<<<1, 128>>>(covs, weights);
    k_quad<<<dim3(BATCH / 128, NMK), 256>>>(means);
    k_out<<<(BATCH * NMK + 255) / 256, 256>>>(out);
}

// round 4
// speedup vs baseline: 2.1461x; 2.1461x over previous
#include <cuda_runtime.h>
#include <cuda_bf16.h>
#include <cstdint>
#include <math.h>

// Problem constants
#define BATCH 4096
#define D_IN  1024
#define DF    256
#define NM    10
#define NK    8
#define NMK   80
#define LOG2PI_F 1.8378770664093453f

// ---------------- scratch (no cudaMalloc allowed) ----------------
__device__ __align__(16) float          g_Ainv[NMK * DF * DF]; // fp32 L^-1 (upper zeroed)
__device__ __align__(16) __nv_bfloat16  g_fhi[BATCH * DF];     // feats hi, [b][d]
__device__ __align__(16) __nv_bfloat16  g_flo[BATCH * DF];     // feats lo
__device__ __align__(16) __nv_bfloat16  g_Bhi[NMK * DF * DF];  // Ainv hi, [mk][d][k]
__device__ __align__(16) __nv_bfloat16  g_Blo[NMK * DF * DF];  // Ainv lo
__device__ float g_v[NMK * DF];                                 // Ainv @ mean (fp32)
__device__ float g_c1[NMK];                                     // -0.5 * w
__device__ float g_c2[NMK];                                     // w*(-0.5*DF*log2pi) - w*logdet

// ---------------- helpers ----------------
__device__ __forceinline__ uint32_t smem_u32(const void* p) {
    uint32_t a;
    asm("{ .reg .u64 t; cvta.to.shared.u64 t, %1; cvt.u32.u64 %0, t; }" : "=r"(a) : "l"(p));
    return a;
}

#define LDSM4(r, addr) \
    asm volatile("ldmatrix.sync.aligned.m8n8.x4.shared.b16 {%0,%1,%2,%3}, [%4];" \
        : "=r"((r)[0]), "=r"((r)[1]), "=r"((r)[2]), "=r"((r)[3]) : "r"(addr))

#define MMA16816(d, a, b) \
    asm volatile("mma.sync.aligned.m16n8k16.row.col.f32.bf16.bf16.f32 " \
        "{%0,%1,%2,%3},{%4,%5,%6,%7},{%8,%9},{%0,%1,%2,%3};" \
        : "+f"((d)[0]), "+f"((d)[1]), "+f"((d)[2]), "+f"((d)[3]) \
        : "r"((a)[0]), "r"((a)[1]), "r"((a)[2]), "r"((a)[3]), "r"((b)[0]), "r"((b)[1]))

// ---------------------------------------------------------------------------
// Kernel 1: feats = relu(x @ W + b), stored as bf16 hi/lo in natural [b][d]
// ---------------------------------------------------------------------------
__global__ __launch_bounds__(256) void k_feats(const float* __restrict__ x,
                                               const float* __restrict__ W,
                                               const float* __restrict__ bias)
{
    const int b0 = blockIdx.x * 128;
    const int n0 = blockIdx.y * 64;
    const int tid = threadIdx.x;
    const int tx = tid & 15;
    const int ty = tid >> 4;

    __shared__ float Xs[16][128];
    __shared__ float Ws[16][64];

    float acc[8][4];
#pragma unroll
    for (int i = 0; i < 8; i++)
#pragma unroll
        for (int j = 0; j < 4; j++) acc[i][j] = 0.0f;

    for (int kt = 0; kt < D_IN; kt += 16) {
        __syncthreads();
#pragma unroll
        for (int it = 0; it < 2; it++) {
            int v = tid + it * 256;
            int row = v >> 2;
            int c4  = (v & 3) * 4;
            float4 xv = *(const float4*)&x[(size_t)(b0 + row) * D_IN + kt + c4];
            Xs[c4 + 0][row] = xv.x;
            Xs[c4 + 1][row] = xv.y;
            Xs[c4 + 2][row] = xv.z;
            Xs[c4 + 3][row] = xv.w;
        }
        {
            int row = tid >> 4;
            int c4  = (tid & 15) * 4;
            *(float4*)&Ws[row][c4] = *(const float4*)&W[(size_t)(kt + row) * DF + n0 + c4];
        }
        __syncthreads();
#pragma unroll
        for (int k = 0; k < 16; k++) {
            float av[8], wv[4];
            float4 a0 = *(float4*)&Xs[k][ty * 8];
            float4 a1 = *(float4*)&Xs[k][ty * 8 + 4];
            av[0] = a0.x; av[1] = a0.y; av[2] = a0.z; av[3] = a0.w;
            av[4] = a1.x; av[5] = a1.y; av[6] = a1.z; av[7] = a1.w;
            float4 w4 = *(float4*)&Ws[k][tx * 4];
            wv[0] = w4.x; wv[1] = w4.y; wv[2] = w4.z; wv[3] = w4.w;
#pragma unroll
            for (int i = 0; i < 8; i++)
#pragma unroll
                for (int j = 0; j < 4; j++)
                    acc[i][j] = fmaf(av[i], wv[j], acc[i][j]);
        }
    }
#pragma unroll
    for (int j = 0; j < 4; j++) {
        int n = n0 + tx * 4 + j;
        float bb = bias[n];
#pragma unroll
        for (int i = 0; i < 8; i++) {
            float v = acc[i][j] + bb;
            v = v > 0.0f ? v : 0.0f;
            __nv_bfloat16 h = __float2bfloat16(v);
            __nv_bfloat16 l = __float2bfloat16(v - __bfloat162float(h));
            size_t idx = (size_t)(b0 + ty * 8 + i) * DF + n;
            g_fhi[idx] = h;
            g_flo[idx] = l;
        }
    }
}

// ---------------------------------------------------------------------------
// Kernel 2: triangular inverse of L = tril(covs[mk]) -> g_Ainv (upper zeroed)
// ---------------------------------------------------------------------------
__global__ __launch_bounds__(256) void k_trinv(const float* __restrict__ covs)
{
    const int mk = blockIdx.x;
    const int cg = blockIdx.y;
    const int w = threadIdx.x >> 5;
    const int lane = threadIdx.x & 31;
    const int g = w * 8 + cg;
    const int j0 = g * 4;

    const float* L = covs + (size_t)mk * DF * DF;
    float* Ai = g_Ainv + (size_t)mk * DF * DF;

    __shared__ float4 xck[8][DF];
    float4* xc = xck[w];

    for (int i = lane; i < j0; i += 32)
        *(float4*)&Ai[i * DF + j0] = make_float4(0.f, 0.f, 0.f, 0.f);

    for (int i = j0; i < DF; i++) {
        float4 s = make_float4(0.f, 0.f, 0.f, 0.f);
        for (int k = j0 + lane; k < i; k += 32) {
            float lik = L[i * DF + k];
            float4 xv = xc[k];
            s.x = fmaf(lik, xv.x, s.x);
            s.y = fmaf(lik, xv.y, s.y);
            s.z = fmaf(lik, xv.z, s.z);
            s.w = fmaf(lik, xv.w, s.w);
        }
#pragma unroll
        for (int off = 16; off > 0; off >>= 1) {
            s.x += __shfl_xor_sync(0xFFFFFFFFu, s.x, off);
            s.y += __shfl_xor_sync(0xFFFFFFFFu, s.y, off);
            s.z += __shfl_xor_sync(0xFFFFFFFFu, s.z, off);
            s.w += __shfl_xor_sync(0xFFFFFFFFu, s.w, off);
        }
        if (lane == 0) {
            float inv = 1.0f / L[i * DF + i];
            float4 xr;
            xr.x = ((i == j0 + 0 ? 1.0f : 0.0f) - s.x) * inv;
            xr.y = ((i == j0 + 1 ? 1.0f : 0.0f) - s.y) * inv;
            xr.z = ((i == j0 + 2 ? 1.0f : 0.0f) - s.z) * inv;
            xr.w = ((i == j0 + 3 ? 1.0f : 0.0f) - s.w) * inv;
            xc[i] = xr;
            *(float4*)&Ai[i * DF + j0] = xr;
        }
        __syncwarp();
    }
}

// ---------------------------------------------------------------------------
// Kernel 3: split g_Ainv -> bf16 hi/lo
// ---------------------------------------------------------------------------
__global__ __launch_bounds__(256) void k_asplit()
{
    size_t idx = ((size_t)blockIdx.x * 256 + threadIdx.x) * 4;
    float4 v = *(const float4*)&g_Ainv[idx];
    __nv_bfloat162 h01, h23, l01, l23;
    h01.x = __float2bfloat16(v.x);  l01.x = __float2bfloat16(v.x - __bfloat162float(h01.x));
    h01.y = __float2bfloat16(v.y);  l01.y = __float2bfloat16(v.y - __bfloat162float(h01.y));
    h23.x = __float2bfloat16(v.z);  l23.x = __float2bfloat16(v.z - __bfloat162float(h23.x));
    h23.y = __float2bfloat16(v.w);  l23.y = __float2bfloat16(v.w - __bfloat162float(h23.y));
    *(__nv_bfloat162*)&g_Bhi[idx]     = h01;
    *(__nv_bfloat162*)&g_Bhi[idx + 2] = h23;
    *(__nv_bfloat162*)&g_Blo[idx]     = l01;
    *(__nv_bfloat162*)&g_Blo[idx + 2] = l23;
}

// ---------------------------------------------------------------------------
// Kernel 4: v[mk][d] = sum_k Ainv[mk][d][k] * mean[mk][k]  (fp32)
// ---------------------------------------------------------------------------
__global__ __launch_bounds__(256) void k_vprep(const float* __restrict__ means)
{
    const int mk = blockIdx.x;
    const int tid = threadIdx.x;
    const int w = tid >> 5;
    const int lane = tid & 31;
    __shared__ float ms[DF];
    ms[tid] = means[mk * DF + tid];
    __syncthreads();
    const float* Ai = g_Ainv + (size_t)mk * DF * DF;
    for (int d = w; d < DF; d += 8) {
        float s = 0.0f;
        for (int k = lane; k < DF; k += 32)
            s = fmaf(Ai[d * DF + k], ms[k], s);
#pragma unroll
        for (int off = 16; off > 0; off >>= 1)
            s += __shfl_xor_sync(0xFFFFFFFFu, s, off);
        if (lane == 0) g_v[mk * DF + d] = s;
    }
}

// ---------------------------------------------------------------------------
// Kernel 5: per-component constants (logdet + softmax weights)
// ---------------------------------------------------------------------------
__global__ void k_prep(const float* __restrict__ covs,
                       const float* __restrict__ weights)
{
    const int mk = threadIdx.x;
    float logdet = 0.0f;
    float wraw = 0.0f;
    if (mk < NMK) {
        const float* L = covs + (size_t)mk * DF * DF;
        for (int i = 0; i < DF; i++) logdet += logf(L[i * DF + i]);
        wraw = weights[mk];
    }
    float mx = wraw;
#pragma unroll
    for (int off = 1; off < 8; off <<= 1)
        mx = fmaxf(mx, __shfl_xor_sync(0xFFFFFFFFu, mx, off));
    float e = (mk < NMK) ? expf(wraw - mx) : 0.0f;
    float sum = e;
#pragma unroll
    for (int off = 1; off < 8; off <<= 1)
        sum += __shfl_xor_sync(0xFFFFFFFFu, sum, off);
    if (mk < NMK) {
        float wsm = e / sum;
        g_c1[mk] = -0.5f * wsm;
        g_c2[mk] = wsm * (-0.5f * (float)DF * LOG2PI_F) - wsm * logdet;
    }
}

// ---------------------------------------------------------------------------
// Kernel 6 (hot): warp-MMA bf16x3 GEMM + fused Mahalanobis epilogue.
// Grid (32 b-tiles, 80 mk), 256 threads (8 warps, 4x2 warp grid, 32x32 tiles).
// For each 64-wide d-block (N), K runs 0..d0+64 (triangular skip).
// out[b][mk] = c1 * sum_d (D[b,d]-v[d])^2 + c2
//
// smem layout (dynamic, 51200 B):
//   FHI [128][64] bf16 @ 0       (16384)
//   FLO                @ 16384   (16384)
//   AHI [64][64]  bf16 @ 32768   (8192)
//   ALO                @ 40960   (8192)
//   V   [256] f32      @ 49152   (1024)
//   Q   [2][128] f32   @ 50176   (1024)
// swizzle: 16B group g of row r stored at group (g ^ (r & 7))
// ---------------------------------------------------------------------------
#define OFQ_FHI 0
#define OFQ_FLO 16384
#define OFQ_AHI 32768
#define OFQ_ALO 40960
#define OFQ_V   49152
#define OFQ_Q   50176
#define QUAD_SMEM 51200

__global__ __launch_bounds__(256) void k_quad_mma(float* __restrict__ out)
{
    extern __shared__ char sm[];
    const uint32_t smb = smem_u32(sm);
    const int tid = threadIdx.x;
    const int lane = tid & 31;
    const int wid = tid >> 5;
    const int warp_m = wid >> 1;      // 0..3  (32 batch rows each)
    const int warp_n = wid & 1;       // 0..1  (32 d cols each)
    const int mk = blockIdx.y;
    const int b0 = blockIdx.x * 128;

    // v into smem
    ((float*)(sm + OFQ_V))[tid] = g_v[mk * DF + tid];

    const __nv_bfloat16* fh = g_fhi + (size_t)b0 * DF;
    const __nv_bfloat16* fl = g_flo + (size_t)b0 * DF;
    const __nv_bfloat16* ah = g_Bhi + (size_t)mk * DF * DF;
    const __nv_bfloat16* al = g_Blo + (size_t)mk * DF * DF;

    // ldmatrix lane address components (fixed per thread)
    // A-operand (F, m16k16 via x4): row = m_base + (l&7) + ((l>>3)&1)*8, gsel = (l>>4)&1
    // B-operand (Amat, 2 n-tiles via x4): row = n_base + (l&7) + ((l>>4)&1)*8, gsel = (l>>3)&1
    const int aRow[2] = { warp_m * 32 +  0 + (lane & 7) + ((lane >> 3) & 1) * 8,
                          warp_m * 32 + 16 + (lane & 7) + ((lane >> 3) & 1) * 8 };
    const int aG = (lane >> 4) & 1;
    const int bRow[2] = { warp_n * 32 +  0 + (lane & 7) + ((lane >> 4) & 1) * 8,
                          warp_n * 32 + 16 + (lane & 7) + ((lane >> 4) & 1) * 8 };
    const int bG = (lane >> 3) & 1;

    uint32_t aAddrBase[2], bAddrBaseH[2], bAddrBaseL[2], aAddrBaseL[2];
#pragma unroll
    for (int i = 0; i < 2; i++) {
        aAddrBase[i]  = smb + OFQ_FHI + aRow[i] * 128;
        aAddrBaseL[i] = smb + OFQ_FLO + aRow[i] * 128;
        bAddrBaseH[i] = smb + OFQ_AHI + bRow[i] * 128;
        bAddrBaseL[i] = smb + OFQ_ALO + bRow[i] * 128;
    }
    const int aXor[2] = { aRow[0] & 7, aRow[1] & 7 };
    const int bXor[2] = { bRow[0] & 7, bRow[1] & 7 };

    // per-thread row-sum accumulators (rows warp_m*32 + lane/4 + i*8)
    float qrow[4] = {0.f, 0.f, 0.f, 0.f};

    for (int dblk = 0; dblk < 4; dblk++) {
        const int nrow0 = dblk * 64;         // A-matrix row offset for this d-block
        float acc[2][4][4];
#pragma unroll
        for (int mt = 0; mt < 2; mt++)
#pragma unroll
            for (int nt = 0; nt < 4; nt++)
#pragma unroll
                for (int r = 0; r < 4; r++) acc[mt][nt][r] = 0.f;

        for (int kc = 0; kc <= dblk; kc++) {
            const int k0 = kc * 64;
            __syncthreads();
            // stage F hi/lo: 128 rows x 8 groups of 16B
#pragma unroll
            for (int it = 0; it < 4; it++) {
                int slot = tid + it * 256;
                int row = slot >> 3, g = slot & 7;
                uint32_t off = (uint32_t)(row * 128 + ((g ^ (row & 7)) << 4));
                const size_t so = (size_t)row * DF + k0 + g * 8;
                *(uint4*)(sm + OFQ_FHI + off) = *(const uint4*)(fh + so);
                *(uint4*)(sm + OFQ_FLO + off) = *(const uint4*)(fl + so);
            }
            // stage Amat hi/lo: 64 rows x 8 groups
#pragma unroll
            for (int it = 0; it < 2; it++) {
                int slot = tid + it * 256;
                int row = slot >> 3, g = slot & 7;
                uint32_t off = (uint32_t)(row * 128 + ((g ^ (row & 7)) << 4));
                const size_t so = (size_t)(nrow0 + row) * DF + k0 + g * 8;
                *(uint4*)(sm + OFQ_AHI + off) = *(const uint4*)(ah + so);
                *(uint4*)(sm + OFQ_ALO + off) = *(const uint4*)(al + so);
            }
            __syncthreads();

#pragma unroll
            for (int ks = 0; ks < 4; ks++) {
                uint32_t fa_hi[2][4], fa_lo[2][4], bm_hi[2][4], bm_lo[2][4];
#pragma unroll
                for (int mt = 0; mt < 2; mt++) {
                    uint32_t ga = (uint32_t)(((ks * 2 + aG) ^ aXor[mt]) << 4);
                    LDSM4(fa_hi[mt], aAddrBase[mt] + ga);
                    LDSM4(fa_lo[mt], aAddrBaseL[mt] + ga);
                }
#pragma unroll
                for (int pr = 0; pr < 2; pr++) {
                    uint32_t gb = (uint32_t)(((ks * 2 + bG) ^ bXor[pr]) << 4);
                    LDSM4(bm_hi[pr], bAddrBaseH[pr] + gb);
                    LDSM4(bm_lo[pr], bAddrBaseL[pr] + gb);
                }
#pragma unroll
                for (int mt = 0; mt < 2; mt++)
#pragma unroll
                    for (int nt = 0; nt < 4; nt++) {
                        uint32_t* bh2 = &bm_hi[nt >> 1][(nt & 1) * 2];
                        uint32_t* bl2 = &bm_lo[nt >> 1][(nt & 1) * 2];
                        MMA16816(acc[mt][nt], fa_hi[mt], bh2);
                        MMA16816(acc[mt][nt], fa_hi[mt], bl2);
                        MMA16816(acc[mt][nt], fa_lo[mt], bh2);
                    }
            }
        }

        // fold this d-block into row sums: z = D - v[d]; qrow += z^2
        const float* vptr = (const float*)(sm + OFQ_V);
#pragma unroll
        for (int mt = 0; mt < 2; mt++)
#pragma unroll
            for (int nt = 0; nt < 4; nt++) {
#pragma unroll
                for (int r = 0; r < 4; r++) {
                    int d = nrow0 + warp_n * 32 + nt * 8 + (lane & 3) * 2 + (r & 1);
                    float z = acc[mt][nt][r] - vptr[d];
                    qrow[mt * 2 + (r >> 1)] = fmaf(z, z, qrow[mt * 2 + (r >> 1)]);
                }
            }
    }

    // reduce across the 4 lanes sharing a row, then across warp_n via smem
    float* qs = (float*)(sm + OFQ_Q);
#pragma unroll
    for (int i = 0; i < 4; i++) {
        float q = qrow[i];
        q += __shfl_xor_sync(0xFFFFFFFFu, q, 1);
        q += __shfl_xor_sync(0xFFFFFFFFu, q, 2);
        if ((lane & 3) == 0)
            qs[warp_n * 128 + warp_m * 32 + (lane >> 2) + i * 8] = q;
    }
    __syncthreads();
    if (tid < 128) {
        float tot = qs[tid] + qs[128 + tid];
        out[(size_t)(b0 + tid) * NMK + mk] = fmaf(g_c1[mk], tot, g_c2[mk]);
    }
}

// ---------------------------------------------------------------------------
extern "C" void kernel_launch(void* const* d_in, const int* in_sizes, int n_in,
                              void* d_out, int out_size)
{
    const float* x       = (const float*)d_in[0];
    const float* W       = (const float*)d_in[1];
    const float* bias    = (const float*)d_in[2];
    const float* means   = (const float*)d_in[3];
    const float* covs    = (const float*)d_in[4];
    const float* weights = (const float*)d_in[5];
    float* out = (float*)d_out;

    cudaFuncSetAttribute(k_quad_mma, cudaFuncAttributeMaxDynamicSharedMemorySize,
                         QUAD_SMEM);

    k_feats<<<dim3(BATCH / 128, DF / 64), 256>>>(x, W, bias);
    k_trinv<<<dim3(NMK, 8), 256>>>(covs);
    k_asplit<<<(NMK * DF * DF) / 1024, 256>>>();
    k_vprep<<<NMK, 256>>>(means);
    k_prep<<<1, 128>>>(covs, weights);
    k_quad_mma<<<dim3(BATCH / 128, NMK), 256, QUAD_SMEM>>>(out);
}

// round 7
// speedup vs baseline: 2.6887x; 1.2528x over previous
#include <cuda_runtime.h>
#include <cuda_bf16.h>
#include <cstdint>
#include <math.h>

// Problem constants
#define BATCH 4096
#define D_IN  1024
#define DF    256
#define NM    10
#define NK    8
#define NMK   80
#define LOG2PI_F 1.8378770664093453f

// ---------------- scratch (no cudaMalloc allowed) ----------------
__device__ __align__(16) float          g_Ainv[NMK * DF * DF]; // fp32 L^-1 (upper zeroed)
__device__ __align__(16) __nv_bfloat16  g_xhi[BATCH * D_IN];   // x hi, [b][k]
__device__ __align__(16) __nv_bfloat16  g_xlo[BATCH * D_IN];   // x lo
__device__ __align__(16) __nv_bfloat16  g_Whi[DF * D_IN];      // W^T hi, [n][k]
__device__ __align__(16) __nv_bfloat16  g_Wlo[DF * D_IN];      // W^T lo
__device__ __align__(16) __nv_bfloat16  g_fhi[BATCH * DF];     // feats hi, [b][d]
__device__ __align__(16) __nv_bfloat16  g_flo[BATCH * DF];     // feats lo
__device__ __align__(16) __nv_bfloat16  g_Bhi[NMK * DF * DF];  // Ainv hi, [mk][d][k]
__device__ __align__(16) __nv_bfloat16  g_Blo[NMK * DF * DF];  // Ainv lo
__device__ float g_v[NMK * DF];                                 // Ainv @ mean (fp32)
__device__ float g_c1[NMK];                                     // -0.5 * w
__device__ float g_c2[NMK];                                     // w*(-0.5*DF*log2pi) - w*logdet

// chunk schedule for k_quad_mma (10 chunks: dblk-major, kc inner)
__constant__ int c_CD[10] = {0, 1, 1, 2, 2, 2, 3, 3, 3, 3};
__constant__ int c_CK[10] = {0, 0, 1, 0, 1, 2, 0, 1, 2, 3};

// ---------------- helpers ----------------
__device__ __forceinline__ uint32_t smem_u32(const void* p) {
    uint32_t a;
    asm("{ .reg .u64 t; cvta.to.shared.u64 t, %1; cvt.u32.u64 %0, t; }" : "=r"(a) : "l"(p));
    return a;
}

#define LDSM4(r, addr) \
    asm volatile("ldmatrix.sync.aligned.m8n8.x4.shared.b16 {%0,%1,%2,%3}, [%4];" \
        : "=r"((r)[0]), "=r"((r)[1]), "=r"((r)[2]), "=r"((r)[3]) : "r"(addr))

#define MMA16816(d, a, b) \
    asm volatile("mma.sync.aligned.m16n8k16.row.col.f32.bf16.bf16.f32 " \
        "{%0,%1,%2,%3},{%4,%5,%6,%7},{%8,%9},{%0,%1,%2,%3};" \
        : "+f"((d)[0]), "+f"((d)[1]), "+f"((d)[2]), "+f"((d)[3]) \
        : "r"((a)[0]), "r"((a)[1]), "r"((a)[2]), "r"((a)[3]), "r"((b)[0]), "r"((b)[1]))

#define CP16(saddr, gptr) \
    asm volatile("cp.async.cg.shared.global [%0], [%1], 16;" :: "r"(saddr), "l"(gptr) : "memory")
#define CP_COMMIT() asm volatile("cp.async.commit_group;" ::: "memory")
#define CP_WAIT1()  asm volatile("cp.async.wait_group 1;" ::: "memory")
#define CP_WAIT0()  asm volatile("cp.async.wait_group 0;" ::: "memory")

// stage buffer internal layout (48 KB per stage):
//   FHI [128][64] bf16 @ 0, FLO @ 16384, AHI [64][64] @ 32768, ALO @ 40960
#define STG_SZ   49152
#define STG_FHI  0
#define STG_FLO  16384
#define STG_AHI  32768
#define STG_ALO  40960

// ---------------------------------------------------------------------------
// split kernels
// ---------------------------------------------------------------------------
__global__ __launch_bounds__(256) void k_xsplit(const float* __restrict__ x)
{
    size_t idx = ((size_t)blockIdx.x * 256 + threadIdx.x) * 4;
    float4 v = *(const float4*)&x[idx];
    __nv_bfloat162 h01, h23, l01, l23;
    h01.x = __float2bfloat16(v.x);  l01.x = __float2bfloat16(v.x - __bfloat162float(h01.x));
    h01.y = __float2bfloat16(v.y);  l01.y = __float2bfloat16(v.y - __bfloat162float(h01.y));
    h23.x = __float2bfloat16(v.z);  l23.x = __float2bfloat16(v.z - __bfloat162float(h23.x));
    h23.y = __float2bfloat16(v.w);  l23.y = __float2bfloat16(v.w - __bfloat162float(h23.y));
    *(__nv_bfloat162*)&g_xhi[idx]     = h01;
    *(__nv_bfloat162*)&g_xhi[idx + 2] = h23;
    *(__nv_bfloat162*)&g_xlo[idx]     = l01;
    *(__nv_bfloat162*)&g_xlo[idx + 2] = l23;
}

// W [k][n] fp32 -> W^T [n][k] bf16 hi/lo
__global__ __launch_bounds__(256) void k_wsplit(const float* __restrict__ W)
{
    const int n = blockIdx.x;
    for (int k = threadIdx.x; k < D_IN; k += 256) {
        float v = W[(size_t)k * DF + n];
        __nv_bfloat16 h = __float2bfloat16(v);
        __nv_bfloat16 l = __float2bfloat16(v - __bfloat162float(h));
        g_Whi[(size_t)n * D_IN + k] = h;
        g_Wlo[(size_t)n * D_IN + k] = l;
    }
}

__global__ __launch_bounds__(256) void k_asplit()
{
    size_t idx = ((size_t)blockIdx.x * 256 + threadIdx.x) * 4;
    float4 v = *(const float4*)&g_Ainv[idx];
    __nv_bfloat162 h01, h23, l01, l23;
    h01.x = __float2bfloat16(v.x);  l01.x = __float2bfloat16(v.x - __bfloat162float(h01.x));
    h01.y = __float2bfloat16(v.y);  l01.y = __float2bfloat16(v.y - __bfloat162float(h01.y));
    h23.x = __float2bfloat16(v.z);  l23.x = __float2bfloat16(v.z - __bfloat162float(h23.x));
    h23.y = __float2bfloat16(v.w);  l23.y = __float2bfloat16(v.w - __bfloat162float(h23.y));
    *(__nv_bfloat162*)&g_Bhi[idx]     = h01;
    *(__nv_bfloat162*)&g_Bhi[idx + 2] = h23;
    *(__nv_bfloat162*)&g_Blo[idx]     = l01;
    *(__nv_bfloat162*)&g_Blo[idx + 2] = l23;
}

// ---------------------------------------------------------------------------
// k_feats_mma: feats = relu(x @ W + b) via bf16x3 warp-MMA, K=1024, 16 chunks.
// Grid (32 b-tiles, 4 n-tiles of 64), 256 threads. Double-buffered cp.async.
// ---------------------------------------------------------------------------
__global__ __launch_bounds__(256) void k_feats_mma(const float* __restrict__ bias)
{
    extern __shared__ char sm[];
    const uint32_t smb = smem_u32(sm);
    const int tid = threadIdx.x;
    const int lane = tid & 31;
    const int wid = tid >> 5;
    const int warp_m = wid >> 1;
    const int warp_n = wid & 1;
    const int b0 = blockIdx.x * 128;
    const int n0 = blockIdx.y * 64;

    const __nv_bfloat16* fh = g_xhi + (size_t)b0 * D_IN;
    const __nv_bfloat16* fl = g_xlo + (size_t)b0 * D_IN;
    const __nv_bfloat16* ah = g_Whi + (size_t)n0 * D_IN;
    const __nv_bfloat16* al = g_Wlo + (size_t)n0 * D_IN;

    const int aRow[2] = { warp_m * 32 +  0 + (lane & 7) + ((lane >> 3) & 1) * 8,
                          warp_m * 32 + 16 + (lane & 7) + ((lane >> 3) & 1) * 8 };
    const int aG = (lane >> 4) & 1;
    const int bRow[2] = { warp_n * 32 +  0 + (lane & 7) + ((lane >> 4) & 1) * 8,
                          warp_n * 32 + 16 + (lane & 7) + ((lane >> 4) & 1) * 8 };
    const int bG = (lane >> 3) & 1;
    const int aXor[2] = { aRow[0] & 7, aRow[1] & 7 };
    const int bXor[2] = { bRow[0] & 7, bRow[1] & 7 };

    auto stage = [&](int j) {
        const uint32_t sb = smb + (uint32_t)(j & 1) * STG_SZ;
        const int k0 = j * 64;
#pragma unroll
        for (int it = 0; it < 4; it++) {
            int slot = tid + it * 256;
            int row = slot >> 3, g = slot & 7;
            uint32_t off = (uint32_t)(row * 128 + ((g ^ (row & 7)) << 4));
            const size_t so = (size_t)row * D_IN + k0 + g * 8;
            CP16(sb + STG_FHI + off, fh + so);
            CP16(sb + STG_FLO + off, fl + so);
        }
#pragma unroll
        for (int it = 0; it < 2; it++) {
            int slot = tid + it * 256;
            int row = slot >> 3, g = slot & 7;
            uint32_t off = (uint32_t)(row * 128 + ((g ^ (row & 7)) << 4));
            const size_t so = (size_t)row * D_IN + k0 + g * 8;
            CP16(sb + STG_AHI + off, ah + so);
            CP16(sb + STG_ALO + off, al + so);
        }
        CP_COMMIT();
    };

    float acc[2][4][4];
#pragma unroll
    for (int mt = 0; mt < 2; mt++)
#pragma unroll
        for (int nt = 0; nt < 4; nt++)
#pragma unroll
            for (int r = 0; r < 4; r++) acc[mt][nt][r] = 0.f;

    stage(0);
#pragma unroll 1
    for (int ci = 0; ci < 16; ci++) {
        if (ci + 1 < 16) { stage(ci + 1); CP_WAIT1(); } else { CP_WAIT0(); }
        __syncthreads();
        const uint32_t sb = smb + (uint32_t)(ci & 1) * STG_SZ;
#pragma unroll
        for (int ks = 0; ks < 4; ks++) {
            uint32_t fa_hi[2][4], fa_lo[2][4], bm_hi[2][4], bm_lo[2][4];
#pragma unroll
            for (int mt = 0; mt < 2; mt++) {
                uint32_t ga = (uint32_t)(((ks * 2 + aG) ^ aXor[mt]) << 4);
                LDSM4(fa_hi[mt], sb + STG_FHI + aRow[mt] * 128 + ga);
                LDSM4(fa_lo[mt], sb + STG_FLO + aRow[mt] * 128 + ga);
            }
#pragma unroll
            for (int pr = 0; pr < 2; pr++) {
                uint32_t gb = (uint32_t)(((ks * 2 + bG) ^ bXor[pr]) << 4);
                LDSM4(bm_hi[pr], sb + STG_AHI + bRow[pr] * 128 + gb);
                LDSM4(bm_lo[pr], sb + STG_ALO + bRow[pr] * 128 + gb);
            }
#pragma unroll
            for (int mt = 0; mt < 2; mt++)
#pragma unroll
                for (int nt = 0; nt < 4; nt++) {
                    uint32_t* bh2 = &bm_hi[nt >> 1][(nt & 1) * 2];
                    uint32_t* bl2 = &bm_lo[nt >> 1][(nt & 1) * 2];
                    MMA16816(acc[mt][nt], fa_hi[mt], bh2);
                    MMA16816(acc[mt][nt], fa_hi[mt], bl2);
                    MMA16816(acc[mt][nt], fa_lo[mt], bh2);
                }
        }
        __syncthreads();
    }

    // epilogue: bias + relu + hi/lo split, bf16x2 stores
#pragma unroll
    for (int nt = 0; nt < 4; nt++) {
        int c = n0 + warp_n * 32 + nt * 8 + (lane & 3) * 2;
        float bc0 = bias[c], bc1 = bias[c + 1];
#pragma unroll
        for (int mt = 0; mt < 2; mt++) {
#pragma unroll
            for (int half = 0; half < 2; half++) {
                int row = b0 + warp_m * 32 + mt * 16 + (lane >> 2) + half * 8;
                float v0 = acc[mt][nt][half * 2 + 0] + bc0;
                float v1 = acc[mt][nt][half * 2 + 1] + bc1;
                v0 = v0 > 0.f ? v0 : 0.f;
                v1 = v1 > 0.f ? v1 : 0.f;
                __nv_bfloat162 h2, l2;
                h2.x = __float2bfloat16(v0); l2.x = __float2bfloat16(v0 - __bfloat162float(h2.x));
                h2.y = __float2bfloat16(v1); l2.y = __float2bfloat16(v1 - __bfloat162float(h2.y));
                *(__nv_bfloat162*)&g_fhi[(size_t)row * DF + c] = h2;
                *(__nv_bfloat162*)&g_flo[(size_t)row * DF + c] = l2;
            }
        }
    }
}

// ---------------------------------------------------------------------------
// Kernel: triangular inverse of L = tril(covs[mk]) -> g_Ainv (upper zeroed)
// ---------------------------------------------------------------------------
__global__ __launch_bounds__(256) void k_trinv(const float* __restrict__ covs)
{
    const int mk = blockIdx.x;
    const int cg = blockIdx.y;
    const int w = threadIdx.x >> 5;
    const int lane = threadIdx.x & 31;
    const int g = w * 8 + cg;
    const int j0 = g * 4;

    const float* L = covs + (size_t)mk * DF * DF;
    float* Ai = g_Ainv + (size_t)mk * DF * DF;

    __shared__ float4 xck[8][DF];
    float4* xc = xck[w];

    for (int i = lane; i < j0; i += 32)
        *(float4*)&Ai[i * DF + j0] = make_float4(0.f, 0.f, 0.f, 0.f);

    for (int i = j0; i < DF; i++) {
        float4 s = make_float4(0.f, 0.f, 0.f, 0.f);
        for (int k = j0 + lane; k < i; k += 32) {
            float lik = L[i * DF + k];
            float4 xv = xc[k];
            s.x = fmaf(lik, xv.x, s.x);
            s.y = fmaf(lik, xv.y, s.y);
            s.z = fmaf(lik, xv.z, s.z);
            s.w = fmaf(lik, xv.w, s.w);
        }
#pragma unroll
        for (int off = 16; off > 0; off >>= 1) {
            s.x += __shfl_xor_sync(0xFFFFFFFFu, s.x, off);
            s.y += __shfl_xor_sync(0xFFFFFFFFu, s.y, off);
            s.z += __shfl_xor_sync(0xFFFFFFFFu, s.z, off);
            s.w += __shfl_xor_sync(0xFFFFFFFFu, s.w, off);
        }
        if (lane == 0) {
            float inv = 1.0f / L[i * DF + i];
            float4 xr;
            xr.x = ((i == j0 + 0 ? 1.0f : 0.0f) - s.x) * inv;
            xr.y = ((i == j0 + 1 ? 1.0f : 0.0f) - s.y) * inv;
            xr.z = ((i == j0 + 2 ? 1.0f : 0.0f) - s.z) * inv;
            xr.w = ((i == j0 + 3 ? 1.0f : 0.0f) - s.w) * inv;
            xc[i] = xr;
            *(float4*)&Ai[i * DF + j0] = xr;
        }
        __syncwarp();
    }
}

// ---------------------------------------------------------------------------
// Kernel: v[mk][d] = sum_k Ainv[mk][d][k] * mean[mk][k]  (grid (80,4))
// ---------------------------------------------------------------------------
__global__ __launch_bounds__(256) void k_vprep(const float* __restrict__ means)
{
    const int mk = blockIdx.x;
    const int d0 = blockIdx.y * 64;
    const int tid = threadIdx.x;
    const int w = tid >> 5;
    const int lane = tid & 31;
    __shared__ float ms[DF];
    ms[tid] = means[mk * DF + tid];
    __syncthreads();
    const float* Ai = g_Ainv + (size_t)mk * DF * DF;
    for (int d = d0 + w; d < d0 + 64; d += 8) {
        float s = 0.0f;
        for (int k = lane; k < DF; k += 32)
            s = fmaf(Ai[d * DF + k], ms[k], s);
#pragma unroll
        for (int off = 16; off > 0; off >>= 1)
            s += __shfl_xor_sync(0xFFFFFFFFu, s, off);
        if (lane == 0) g_v[mk * DF + d] = s;
    }
}

// ---------------------------------------------------------------------------
// Kernel: per-component constants, one warp per mk (grid 80, block 32)
// ---------------------------------------------------------------------------
__global__ __launch_bounds__(32) void k_prep(const float* __restrict__ covs,
                                             const float* __restrict__ weights)
{
    const int mk = blockIdx.x;
    const int lane = threadIdx.x;
    const float* L = covs + (size_t)mk * DF * DF;
    float logdet = 0.0f;
    for (int i = lane; i < DF; i += 32)
        logdet += logf(L[i * DF + i]);
#pragma unroll
    for (int off = 16; off > 0; off >>= 1)
        logdet += __shfl_xor_sync(0xFFFFFFFFu, logdet, off);
    if (lane == 0) {
        const int m = mk >> 3;
        float wk[NK];
        float mx = -1e30f;
#pragma unroll
        for (int j = 0; j < NK; j++) { wk[j] = weights[m * NK + j]; mx = fmaxf(mx, wk[j]); }
        float sum = 0.f;
#pragma unroll
        for (int j = 0; j < NK; j++) sum += expf(wk[j] - mx);
        float wsm = expf(weights[mk] - mx) / sum;
        g_c1[mk] = -0.5f * wsm;
        g_c2[mk] = wsm * (-0.5f * (float)DF * LOG2PI_F) - wsm * logdet;
    }
}

// ---------------------------------------------------------------------------
// Kernel (hot): warp-MMA bf16x3 GEMM + fused Mahalanobis epilogue.
// Double-buffered cp.async pipeline over 10 (dblk,kc) chunks.
// ---------------------------------------------------------------------------
#define OFQ_V   (2 * STG_SZ)          // 98304
#define OFQ_Q   (2 * STG_SZ + 1024)   // 99328
#define QUAD_SMEM (2 * STG_SZ + 2048) // 100352

__global__ __launch_bounds__(256) void k_quad_mma(float* __restrict__ out)
{
    extern __shared__ char sm[];
    const uint32_t smb = smem_u32(sm);
    const int tid = threadIdx.x;
    const int lane = tid & 31;
    const int wid = tid >> 5;
    const int warp_m = wid >> 1;
    const int warp_n = wid & 1;
    const int mk = blockIdx.y;
    const int b0 = blockIdx.x * 128;

    ((float*)(sm + OFQ_V))[tid] = g_v[mk * DF + tid];

    const __nv_bfloat16* fh = g_fhi + (size_t)b0 * DF;
    const __nv_bfloat16* fl = g_flo + (size_t)b0 * DF;
    const __nv_bfloat16* ah = g_Bhi + (size_t)mk * DF * DF;
    const __nv_bfloat16* al = g_Blo + (size_t)mk * DF * DF;

    const int aRow[2] = { warp_m * 32 +  0 + (lane & 7) + ((lane >> 3) & 1) * 8,
                          warp_m * 32 + 16 + (lane & 7) + ((lane >> 3) & 1) * 8 };
    const int aG = (lane >> 4) & 1;
    const int bRow[2] = { warp_n * 32 +  0 + (lane & 7) + ((lane >> 4) & 1) * 8,
                          warp_n * 32 + 16 + (lane & 7) + ((lane >> 4) & 1) * 8 };
    const int bG = (lane >> 3) & 1;
    const int aXor[2] = { aRow[0] & 7, aRow[1] & 7 };
    const int bXor[2] = { bRow[0] & 7, bRow[1] & 7 };

    auto stage = [&](int j) {
        const uint32_t sb = smb + (uint32_t)(j & 1) * STG_SZ;
        const int k0 = c_CK[j] * 64;
        const int ar0 = c_CD[j] * 64;
#pragma unroll
        for (int it = 0; it < 4; it++) {
            int slot = tid + it * 256;
            int row = slot >> 3, g = slot & 7;
            uint32_t off = (uint32_t)(row * 128 + ((g ^ (row & 7)) << 4));
            const size_t so = (size_t)row * DF + k0 + g * 8;
            CP16(sb + STG_FHI + off, fh + so);
            CP16(sb + STG_FLO + off, fl + so);
        }
#pragma unroll
        for (int it = 0; it < 2; it++) {
            int slot = tid + it * 256;
            int row = slot >> 3, g = slot & 7;
            uint32_t off = (uint32_t)(row * 128 + ((g ^ (row & 7)) << 4));
            const size_t so = (size_t)(ar0 + row) * DF + k0 + g * 8;
            CP16(sb + STG_AHI + off, ah + so);
            CP16(sb + STG_ALO + off, al + so);
        }
        CP_COMMIT();
    };

    float qrow[4] = {0.f, 0.f, 0.f, 0.f};
    const float* vptr = (const float*)(sm + OFQ_V);

    stage(0);
    int ci = 0;
#pragma unroll 1
    for (int dblk = 0; dblk < 4; dblk++) {
        const int nrow0 = dblk * 64;
        float acc[2][4][4];
#pragma unroll
        for (int mt = 0; mt < 2; mt++)
#pragma unroll
            for (int nt = 0; nt < 4; nt++)
#pragma unroll
                for (int r = 0; r < 4; r++) acc[mt][nt][r] = 0.f;

#pragma unroll 1
        for (int kc = 0; kc <= dblk; kc++) {
            if (ci + 1 < 10) { stage(ci + 1); CP_WAIT1(); } else { CP_WAIT0(); }
            __syncthreads();
            const uint32_t sb = smb + (uint32_t)(ci & 1) * STG_SZ;
#pragma unroll
            for (int ks = 0; ks < 4; ks++) {
                uint32_t fa_hi[2][4], fa_lo[2][4], bm_hi[2][4], bm_lo[2][4];
#pragma unroll
                for (int mt = 0; mt < 2; mt++) {
                    uint32_t ga = (uint32_t)(((ks * 2 + aG) ^ aXor[mt]) << 4);
                    LDSM4(fa_hi[mt], sb + STG_FHI + aRow[mt] * 128 + ga);
                    LDSM4(fa_lo[mt], sb + STG_FLO + aRow[mt] * 128 + ga);
                }
#pragma unroll
                for (int pr = 0; pr < 2; pr++) {
                    uint32_t gb = (uint32_t)(((ks * 2 + bG) ^ bXor[pr]) << 4);
                    LDSM4(bm_hi[pr], sb + STG_AHI + bRow[pr] * 128 + gb);
                    LDSM4(bm_lo[pr], sb + STG_ALO + bRow[pr] * 128 + gb);
                }
#pragma unroll
                for (int mt = 0; mt < 2; mt++)
#pragma unroll
                    for (int nt = 0; nt < 4; nt++) {
                        uint32_t* bh2 = &bm_hi[nt >> 1][(nt & 1) * 2];
                        uint32_t* bl2 = &bm_lo[nt >> 1][(nt & 1) * 2];
                        MMA16816(acc[mt][nt], fa_hi[mt], bh2);
                        MMA16816(acc[mt][nt], fa_hi[mt], bl2);
                        MMA16816(acc[mt][nt], fa_lo[mt], bh2);
                    }
            }
            __syncthreads();
            ci++;
        }

        // fold: z = D - v[d]; qrow += z^2
#pragma unroll
        for (int mt = 0; mt < 2; mt++)
#pragma unroll
            for (int nt = 0; nt < 4; nt++) {
#pragma unroll
                for (int r = 0; r < 4; r++) {
                    int d = nrow0 + warp_n * 32 + nt * 8 + (lane & 3) * 2 + (r & 1);
                    float z = acc[mt][nt][r] - vptr[d];
                    qrow[mt * 2 + (r >> 1)] = fmaf(z, z, qrow[mt * 2 + (r >> 1)]);
                }
            }
    }

    float* qs = (float*)(sm + OFQ_Q);
#pragma unroll
    for (int i = 0; i < 4; i++) {
        float q = qrow[i];
        q += __shfl_xor_sync(0xFFFFFFFFu, q, 1);
        q += __shfl_xor_sync(0xFFFFFFFFu, q, 2);
        if ((lane & 3) == 0)
            qs[warp_n * 128 + warp_m * 32 + (lane >> 2) + i * 8] = q;
    }
    __syncthreads();
    if (tid < 128) {
        float tot = qs[tid] + qs[128 + tid];
        out[(size_t)(b0 + tid) * NMK + mk] = fmaf(g_c1[mk], tot, g_c2[mk]);
    }
}

// ---------------------------------------------------------------------------
extern "C" void kernel_launch(void* const* d_in, const int* in_sizes, int n_in,
                              void* d_out, int out_size)
{
    const float* x       = (const float*)d_in[0];
    const float* W       = (const float*)d_in[1];
    const float* bias    = (const float*)d_in[2];
    const float* means   = (const float*)d_in[3];
    const float* covs    = (const float*)d_in[4];
    const float* weights = (const float*)d_in[5];
    float* out = (float*)d_out;

    cudaFuncSetAttribute(k_quad_mma, cudaFuncAttributeMaxDynamicSharedMemorySize,
                         QUAD_SMEM);
    cudaFuncSetAttribute(k_feats_mma, cudaFuncAttributeMaxDynamicSharedMemorySize,
                         2 * STG_SZ);

    k_xsplit<<<(BATCH * D_IN) / 1024, 256>>>(x);
    k_wsplit<<<DF, 256>>>(W);
    k_trinv<<<dim3(NMK, 8), 256>>>(covs);
    k_feats_mma<<<dim3(BATCH / 128, DF / 64), 256, 2 * STG_SZ>>>(bias);
    k_asplit<<<(NMK * DF * DF) / 1024, 256>>>();
    k_vprep<<<dim3(NMK, 4), 256>>>(means);
    k_prep<<<NMK, 32>>>(covs, weights);
    k_quad_mma<<<dim3(BATCH / 128, NMK), 256, QUAD_SMEM>>>(out);
}